// round 1
// baseline (speedup 1.0000x reference)
#include <cuda_runtime.h>

// SBNet block-sparse 3x3 conv, fp32, packed f32x2 FMA path.
// Layouts: x[N=4][C=64][448][448], mask[4][1][448][448],
//          weight[O=64][C=64][3][3], bias[64], out[4][64][448][448].
// Block grid: 32x32 blocks of 14x14 outputs per image; active iff
// max(mask over 16x16 window at offset -1) > 0.5.

namespace {
constexpr int Himg = 448, Wimg = 448, Cin = 64, Cout = 64;
constexpr int BS = 14;
constexpr int NBLK = 32 * 32;      // blocks per image
constexpr int TPB = 224;           // 14 rows x 16 cout-groups
constexpr int WS_K_STRIDE = 65;    // padded to kill STS bank conflicts
constexpr int WS_C_STRIDE = 9 * WS_K_STRIDE;   // 585
constexpr int XS_FLOATS = Cin * 256;           // 16384 (16x16 tile per c)
constexpr int WS_FLOATS = Cin * WS_C_STRIDE;   // 37440
constexpr int SMEM_BYTES = (XS_FLOATS + WS_FLOATS) * 4;  // 215296 B
}

__device__ __forceinline__ unsigned long long pk2(float lo, float hi) {
    unsigned long long r;
    asm("mov.b64 %0, {%1,%2};" : "=l"(r) : "f"(lo), "f"(hi));
    return r;
}
__device__ __forceinline__ void fma2(unsigned long long& d,
                                     unsigned long long a,
                                     unsigned long long b) {
    asm("fma.rn.f32x2 %0, %1, %2, %0;" : "+l"(d) : "l"(a), "l"(b));
}

__global__ __launch_bounds__(TPB, 1)
void sbnet_conv_kernel(const float* __restrict__ x,
                       const float* __restrict__ mask,
                       const float* __restrict__ weight,
                       const float* __restrict__ bias,
                       float* __restrict__ out) {
    extern __shared__ float smem[];
    float* xs = smem;                 // [c][16][16]
    float* ws = smem + XS_FLOATS;     // [c][k(pad 65)][o]

    const int b  = blockIdx.x;
    const int n  = b >> 10;
    const int rem = b & (NBLK - 1);
    const int by = rem >> 5, bx = rem & 31;
    const int t  = threadIdx.x;
    const int y0 = by * BS, x0 = bx * BS;

    // ---- block activity: max of mask over 16x16 gather window ----
    float mv = 0.f;
    const float* mplane = mask + (size_t)n * Himg * Wimg;
    for (int i = t; i < 256; i += TPB) {
        int ty = i >> 4, tx = i & 15;
        int gy = y0 - 1 + ty, gx = x0 - 1 + tx;
        if ((unsigned)gy < (unsigned)Himg && (unsigned)gx < (unsigned)Wimg)
            mv = fmaxf(mv, mplane[gy * Wimg + gx]);
    }
    const int act = __syncthreads_or(mv > 0.5f);

    const int r  = t >> 4;   // output row 0..13
    const int cg = t & 15;   // cout group (4 couts each)
    const int obase0 = ((n * Cout + cg * 4) * Himg + (y0 + r)) * Wimg + x0;

    if (!act) {  // inactive: write zeros (out buffer is poisoned)
        const float2 z = make_float2(0.f, 0.f);
        #pragma unroll
        for (int oi = 0; oi < 4; oi++) {
            float2* op = (float2*)(out + obase0 + oi * Himg * Wimg);
            #pragma unroll
            for (int j = 0; j < 7; j++) op[j] = z;
        }
        return;
    }

    // ---- stage input tile (with 1px halo, zero-padded) ----
    const float* xpl = x + (size_t)n * Cin * Himg * Wimg;
    for (int i = t; i < XS_FLOATS; i += TPB) {
        int c = i >> 8, p = i & 255;
        int ty = p >> 4, tx = p & 15;
        int gy = y0 - 1 + ty, gx = x0 - 1 + tx;
        float v = 0.f;
        if ((unsigned)gy < (unsigned)Himg && (unsigned)gx < (unsigned)Wimg)
            v = xpl[(c * Himg + gy) * Wimg + gx];
        xs[i] = v;
    }
    // ---- stage weights: global [o][c][k] -> smem [c][k][o] ----
    for (int i = t; i < Cout * Cin * 9; i += TPB) {
        int o  = i / 576;
        int r2 = i - o * 576;
        int c  = r2 / 9;
        int k  = r2 - c * 9;
        ws[c * WS_C_STRIDE + k * WS_K_STRIDE + o] = weight[i];
    }
    __syncthreads();

    // ---- compute: 14 px (as 7 f32x2 pairs) x 4 couts per thread ----
    unsigned long long acc[4][7];
    #pragma unroll
    for (int oi = 0; oi < 4; oi++)
        #pragma unroll
        for (int j = 0; j < 7; j++) acc[oi][j] = 0ULL;  // bits of (0.f,0.f)

    for (int c = 0; c < Cin; c++) {
        const float* xr = xs + c * 256;
        const float* wr = ws + c * WS_C_STRIDE;
        #pragma unroll
        for (int dy = 0; dy < 3; dy++) {
            const float4* rowp = (const float4*)(xr + (r + dy) * 16);
            float4 a0 = rowp[0], a1 = rowp[1], a2 = rowp[2], a3 = rowp[3];
            float v[16] = {a0.x, a0.y, a0.z, a0.w, a1.x, a1.y, a1.z, a1.w,
                           a2.x, a2.y, a2.z, a2.w, a3.x, a3.y, a3.z, a3.w};
            unsigned long long pe[8], po[7];
            #pragma unroll
            for (int j = 0; j < 8; j++) pe[j] = pk2(v[2 * j], v[2 * j + 1]);
            #pragma unroll
            for (int j = 0; j < 7; j++) po[j] = pk2(v[2 * j + 1], v[2 * j + 2]);
            #pragma unroll
            for (int oi = 0; oi < 4; oi++) {
                const int o = cg * 4 + oi;
                float w0 = wr[(dy * 3 + 0) * WS_K_STRIDE + o];
                float w1 = wr[(dy * 3 + 1) * WS_K_STRIDE + o];
                float w2 = wr[(dy * 3 + 2) * WS_K_STRIDE + o];
                unsigned long long W0 = pk2(w0, w0);
                unsigned long long W1 = pk2(w1, w1);
                unsigned long long W2 = pk2(w2, w2);
                #pragma unroll
                for (int j = 0; j < 7; j++) {
                    fma2(acc[oi][j], pe[j],     W0);
                    fma2(acc[oi][j], po[j],     W1);
                    fma2(acc[oi][j], pe[j + 1], W2);
                }
            }
        }
    }

    // ---- epilogue: add bias, store as float2 (x0 even -> aligned) ----
    #pragma unroll
    for (int oi = 0; oi < 4; oi++) {
        const float bo = __ldg(bias + cg * 4 + oi);
        float* op = out + obase0 + oi * Himg * Wimg;
        #pragma unroll
        for (int j = 0; j < 7; j++) {
            float2 f = *(float2*)&acc[oi][j];
            f.x += bo; f.y += bo;
            *(float2*)(op + 2 * j) = f;
        }
    }
}

extern "C" void kernel_launch(void* const* d_in, const int* in_sizes, int n_in,
                              void* d_out, int out_size) {
    const float* x      = (const float*)d_in[0];
    const float* mask   = (const float*)d_in[1];
    const float* weight = (const float*)d_in[2];
    const float* bias   = (const float*)d_in[3];
    float* out = (float*)d_out;

    cudaFuncSetAttribute(sbnet_conv_kernel,
                         cudaFuncAttributeMaxDynamicSharedMemorySize, SMEM_BYTES);
    sbnet_conv_kernel<<<4 * NBLK, TPB, SMEM_BYTES>>>(x, mask, weight, bias, out);
}

// round 2
// speedup vs baseline: 1.2341x; 1.2341x over previous
#include <cuda_runtime.h>

// SBNet block-sparse 3x3 conv, fp32, packed f32x2 FMA path. R2: 448 threads
// (14 warps/SM) for latency hiding; 2 couts/thread; aligned LDS.64 weight pairs.
// Layouts: x[4][64][448][448], mask[4][1][448][448], weight[64][64][3][3],
// bias[64], out[4][64][448][448]. 14x14 output blocks; active iff
// max(mask over 16x16 window at offset -1) > 0.5.

namespace {
constexpr int Himg = 448, Wimg = 448, Cin = 64, Cout = 64;
constexpr int BS = 14;
constexpr int NBLK = 32 * 32;      // blocks per image
constexpr int TPB = 448;           // 14 rows x 32 cout-pairs
constexpr int WS_K_STRIDE = 66;    // even (aligned LDS.64) + bank-spread (66%32=2)
constexpr int WS_C_STRIDE = 9 * WS_K_STRIDE;   // 594
constexpr int XS_FLOATS = Cin * 256;           // 16384 (16x16 tile per c)
constexpr int WS_FLOATS = Cin * WS_C_STRIDE;   // 38016
constexpr int SMEM_BYTES = (XS_FLOATS + WS_FLOATS) * 4;  // 217600 B
}

__device__ __forceinline__ unsigned long long pk2(float lo, float hi) {
    unsigned long long r;
    asm("mov.b64 %0, {%1,%2};" : "=l"(r) : "f"(lo), "f"(hi));
    return r;
}
__device__ __forceinline__ void fma2(unsigned long long& d,
                                     unsigned long long a,
                                     unsigned long long b) {
    asm("fma.rn.f32x2 %0, %1, %2, %0;" : "+l"(d) : "l"(a), "l"(b));
}

__global__ __launch_bounds__(TPB, 1)
void sbnet_conv_kernel(const float* __restrict__ x,
                       const float* __restrict__ mask,
                       const float* __restrict__ weight,
                       const float* __restrict__ bias,
                       float* __restrict__ out) {
    extern __shared__ float smem[];
    float* xs = smem;                 // [c][16][16]
    float* ws = smem + XS_FLOATS;     // [c][k(stride 66)][o]

    const int b   = blockIdx.x;
    const int n   = b >> 10;
    const int rem = b & (NBLK - 1);
    const int by  = rem >> 5, bx = rem & 31;
    const int t   = threadIdx.x;
    const int y0  = by * BS, x0 = bx * BS;

    // ---- block activity: max of mask over 16x16 gather window ----
    float mv = 0.f;
    const float* mplane = mask + (size_t)n * Himg * Wimg;
    if (t < 256) {
        int ty = t >> 4, tx = t & 15;
        int gy = y0 - 1 + ty, gx = x0 - 1 + tx;
        if ((unsigned)gy < (unsigned)Himg && (unsigned)gx < (unsigned)Wimg)
            mv = mplane[gy * Wimg + gx];
    }
    const int act = __syncthreads_or(mv > 0.5f);

    const int r  = t >> 5;    // output row 0..13
    const int cg = t & 31;    // cout pair index (2 couts each)
    const int obase0 = ((n * Cout + cg * 2) * Himg + (y0 + r)) * Wimg + x0;

    if (!act) {  // inactive: write zeros (out buffer is poisoned)
        const float2 z = make_float2(0.f, 0.f);
        #pragma unroll
        for (int oi = 0; oi < 2; oi++) {
            float2* op = (float2*)(out + obase0 + oi * Himg * Wimg);
            #pragma unroll
            for (int j = 0; j < 7; j++) op[j] = z;
        }
        return;
    }

    // ---- stage input tile (with 1px halo, zero-padded) ----
    const float* xpl = x + (size_t)n * Cin * Himg * Wimg;
    for (int i = t; i < XS_FLOATS; i += TPB) {
        int c = i >> 8, p = i & 255;
        int ty = p >> 4, tx = p & 15;
        int gy = y0 - 1 + ty, gx = x0 - 1 + tx;
        float v = 0.f;
        if ((unsigned)gy < (unsigned)Himg && (unsigned)gx < (unsigned)Wimg)
            v = xpl[(c * Himg + gy) * Wimg + gx];
        xs[i] = v;
    }
    // ---- stage weights: global [o][c][k] (coalesced reads) -> smem [c][k][o]
    for (int i = t; i < Cout * Cin * 9; i += TPB) {
        int o  = i / 576;                  // global index order: o slow
        int r2 = i - o * 576;
        int c  = r2 / 9;
        int k  = r2 - c * 9;
        ws[c * WS_C_STRIDE + k * WS_K_STRIDE + o] = weight[i];
    }
    __syncthreads();

    // ---- compute: 14 px (7 f32x2 pairs) x 2 couts per thread ----
    unsigned long long acc[2][7];
    #pragma unroll
    for (int oi = 0; oi < 2; oi++)
        #pragma unroll
        for (int j = 0; j < 7; j++) acc[oi][j] = 0ULL;  // bits of (0.f,0.f)

    const float* wbase = ws + cg * 2;

    #pragma unroll 2
    for (int c = 0; c < Cin; c++) {
        const float* xr = xs + c * 256;
        const float* wr = wbase + c * WS_C_STRIDE;
        #pragma unroll
        for (int dy = 0; dy < 3; dy++) {
            const float4* rowp = (const float4*)(xr + (r + dy) * 16);
            float4 a0 = rowp[0], a1 = rowp[1], a2 = rowp[2], a3 = rowp[3];
            float v[16] = {a0.x, a0.y, a0.z, a0.w, a1.x, a1.y, a1.z, a1.w,
                           a2.x, a2.y, a2.z, a2.w, a3.x, a3.y, a3.z, a3.w};
            unsigned long long pe[8], po[7];
            #pragma unroll
            for (int j = 0; j < 8; j++) pe[j] = pk2(v[2 * j], v[2 * j + 1]);
            #pragma unroll
            for (int j = 0; j < 7; j++) po[j] = pk2(v[2 * j + 1], v[2 * j + 2]);

            // aligned float2 weight loads: both couts for each tap
            float2 wp0 = *(const float2*)(wr + (dy * 3 + 0) * WS_K_STRIDE);
            float2 wp1 = *(const float2*)(wr + (dy * 3 + 1) * WS_K_STRIDE);
            float2 wp2 = *(const float2*)(wr + (dy * 3 + 2) * WS_K_STRIDE);
            unsigned long long W[2][3] = {
                {pk2(wp0.x, wp0.x), pk2(wp1.x, wp1.x), pk2(wp2.x, wp2.x)},
                {pk2(wp0.y, wp0.y), pk2(wp1.y, wp1.y), pk2(wp2.y, wp2.y)}};
            #pragma unroll
            for (int oi = 0; oi < 2; oi++) {
                #pragma unroll
                for (int j = 0; j < 7; j++) {
                    fma2(acc[oi][j], pe[j],     W[oi][0]);
                    fma2(acc[oi][j], po[j],     W[oi][1]);
                    fma2(acc[oi][j], pe[j + 1], W[oi][2]);
                }
            }
        }
    }

    // ---- epilogue: add bias, store as float2 (x0 even -> aligned) ----
    #pragma unroll
    for (int oi = 0; oi < 2; oi++) {
        const float bo = __ldg(bias + cg * 2 + oi);
        float* op = out + obase0 + oi * Himg * Wimg;
        #pragma unroll
        for (int j = 0; j < 7; j++) {
            float2 f = *(float2*)&acc[oi][j];
            f.x += bo; f.y += bo;
            *(float2*)(op + 2 * j) = f;
        }
    }
}

extern "C" void kernel_launch(void* const* d_in, const int* in_sizes, int n_in,
                              void* d_out, int out_size) {
    const float* x      = (const float*)d_in[0];
    const float* mask   = (const float*)d_in[1];
    const float* weight = (const float*)d_in[2];
    const float* bias   = (const float*)d_in[3];
    float* out = (float*)d_out;

    cudaFuncSetAttribute(sbnet_conv_kernel,
                         cudaFuncAttributeMaxDynamicSharedMemorySize, SMEM_BYTES);
    sbnet_conv_kernel<<<4 * NBLK, TPB, SMEM_BYTES>>>(x, mask, weight, bias, out);
}